// round 1
// baseline (speedup 1.0000x reference)
#include <cuda_runtime.h>
#include <math.h>

// ---------------- scratch (device globals; no allocations allowed) ----------
__device__ float g_q[8192 * 4096];
__device__ float g_k[8192 * 4096];
__device__ float g_v[8192 * 4096];
__device__ float g_ep[67108864]; // 8192*8192

// ---------------- helpers ----------------------------------------------------
__device__ __forceinline__ unsigned f2tf(float x) {
    unsigned u;
    asm("cvt.rna.tf32.f32 %0, %1;" : "=r"(u) : "f"(x));
    return u;
}

#define MMA8(C, A, Bv)                                                         \
    asm volatile(                                                              \
        "mma.sync.aligned.m16n8k8.row.col.f32.tf32.tf32.f32 "                  \
        "{%0,%1,%2,%3}, {%4,%5,%6,%7}, {%8,%9}, {%0,%1,%2,%3};"                \
        : "+f"(C[0]), "+f"(C[1]), "+f"(C[2]), "+f"(C[3])                       \
        : "r"(A[0]), "r"(A[1]), "r"(A[2]), "r"(A[3]), "r"(Bv[0]), "r"(Bv[1]))

// ---------------- GEMM: C[M,N] = A[M,K] * B[N,K]^T (+bias[n]) ---------------
// tf32 tensor-core GEMM, 128x128x32 block tile, 8 warps (2m x 4n), 64x32 warp tile
#define GBM 128
#define GBN 128
#define GBK 32
#define GSTR 36                    // 36 % 32 == 4 -> conflict-free frag loads
#define GSTAGE (GBM * GSTR)        // floats per stage per matrix
#define GEMM_SMEM (4 * GSTAGE * 4) // 2 stages * (A+B) * 4B = 73728 B

__global__ void __launch_bounds__(256, 1)
    gemm_tf32(const float* __restrict__ A, const float* __restrict__ B,
              const float* __restrict__ bias, float* __restrict__ C,
              int M, int N, int K) {
    extern __shared__ float sm[];
    float* As = sm;                // [2][128][36]
    float* Bs = sm + 2 * GSTAGE;   // [2][128][36]

    const int tid = threadIdx.x;
    const int lane = tid & 31;
    const int wid = tid >> 5;
    const int g = lane >> 2;   // 0..7
    const int t4 = lane & 3;   // 0..3
    const int wm = (wid & 1) * 64;
    const int wn = (wid >> 1) * 32;

    const int bm = blockIdx.y * GBM;
    const int bn = blockIdx.x * GBN;

    const int lrow = tid >> 3;        // 0..31
    const int lcol = (tid & 7) * 4;   // 0,4,...,28

    const float* Ag = A + (size_t)(bm + lrow) * K + lcol;
    const float* Bg = B + (size_t)(bn + lrow) * K + lcol;

    float4 ra[4], rb[4];

    // prologue: load tile 0
#pragma unroll
    for (int i = 0; i < 4; i++) {
        ra[i] = *(const float4*)(Ag + (size_t)i * 32 * K);
        rb[i] = *(const float4*)(Bg + (size_t)i * 32 * K);
    }
#pragma unroll
    for (int i = 0; i < 4; i++) {
        *(uint4*)(As + (lrow + i * 32) * GSTR + lcol) =
            make_uint4(f2tf(ra[i].x), f2tf(ra[i].y), f2tf(ra[i].z), f2tf(ra[i].w));
        *(uint4*)(Bs + (lrow + i * 32) * GSTR + lcol) =
            make_uint4(f2tf(rb[i].x), f2tf(rb[i].y), f2tf(rb[i].z), f2tf(rb[i].w));
    }

    float c[4][4][4];
#pragma unroll
    for (int i = 0; i < 4; i++)
#pragma unroll
        for (int j = 0; j < 4; j++)
#pragma unroll
            for (int q = 0; q < 4; q++) c[i][j][q] = 0.f;

    const int NT = K / GBK;
    for (int kt = 0; kt < NT; kt++) {
        if (kt + 1 < NT) {
#pragma unroll
            for (int i = 0; i < 4; i++) {
                ra[i] = *(const float4*)(Ag + (size_t)(kt + 1) * GBK + (size_t)i * 32 * K);
                rb[i] = *(const float4*)(Bg + (size_t)(kt + 1) * GBK + (size_t)i * 32 * K);
            }
        }
        __syncthreads();
        const float* as = As + (kt & 1) * GSTAGE;
        const float* bs = Bs + (kt & 1) * GSTAGE;
#pragma unroll
        for (int ks = 0; ks < 4; ks++) {
            const int k0 = ks * 8;
            unsigned af[4][4], bf[4][2];
#pragma unroll
            for (int mf = 0; mf < 4; mf++) {
                const float* p = as + (wm + mf * 16 + g) * GSTR + k0 + t4;
                af[mf][0] = __float_as_uint(p[0]);
                af[mf][1] = __float_as_uint(p[8 * GSTR]);
                af[mf][2] = __float_as_uint(p[4]);
                af[mf][3] = __float_as_uint(p[8 * GSTR + 4]);
            }
#pragma unroll
            for (int nf = 0; nf < 4; nf++) {
                const float* p = bs + (wn + nf * 8 + g) * GSTR + k0 + t4;
                bf[nf][0] = __float_as_uint(p[0]);
                bf[nf][1] = __float_as_uint(p[4]);
            }
#pragma unroll
            for (int mf = 0; mf < 4; mf++)
#pragma unroll
                for (int nf = 0; nf < 4; nf++) MMA8(c[mf][nf], af[mf], bf[nf]);
        }
        if (kt + 1 < NT) {
            float* asw = As + ((kt + 1) & 1) * GSTAGE;
            float* bsw = Bs + ((kt + 1) & 1) * GSTAGE;
#pragma unroll
            for (int i = 0; i < 4; i++) {
                *(uint4*)(asw + (lrow + i * 32) * GSTR + lcol) =
                    make_uint4(f2tf(ra[i].x), f2tf(ra[i].y), f2tf(ra[i].z), f2tf(ra[i].w));
                *(uint4*)(bsw + (lrow + i * 32) * GSTR + lcol) =
                    make_uint4(f2tf(rb[i].x), f2tf(rb[i].y), f2tf(rb[i].z), f2tf(rb[i].w));
            }
        }
    }

    // epilogue
#pragma unroll
    for (int mf = 0; mf < 4; mf++) {
        const int r0 = bm + wm + mf * 16 + g;
#pragma unroll
        for (int nf = 0; nf < 4; nf++) {
            const int col = bn + wn + nf * 8 + 2 * t4;
            float b0 = 0.f, b1 = 0.f;
            if (bias) { b0 = bias[col]; b1 = bias[col + 1]; }
            *(float2*)(C + (size_t)r0 * N + col) =
                make_float2(c[mf][nf][0] + b0, c[mf][nf][1] + b1);
            *(float2*)(C + (size_t)(r0 + 8) * N + col) =
                make_float2(c[mf][nf][2] + b0, c[mf][nf][3] + b1);
        }
    }
}

// ---------------- fused attention --------------------------------------------
// One block = (batch b, head h, 64-query tile). Flash-style over 64-key chunks.
// S = (Q*scale) K^T via tf32 mma, + ep bias, online softmax, O += P V via mma.
#define AQ 64
#define AS 64
#define QSTR 260
#define KSTR 260
#define VSTR 264
#define SSTR 68
#define ATTN_SMEM ((AQ * QSTR + AS * KSTR + AS * VSTR + AQ * SSTR + 3 * AQ) * 4)

__global__ void __launch_bounds__(256, 1)
    attn_tf32(const float* __restrict__ Q, const float* __restrict__ Kk,
              const float* __restrict__ V, const float* __restrict__ EP,
              float* __restrict__ O) {
    extern __shared__ float sm[];
    float* Qs = sm;
    float* Ks = Qs + AQ * QSTR;
    float* Vs = Ks + AS * KSTR;
    float* Ss = Vs + AS * VSTR;
    float* rM = Ss + AQ * SSTR;
    float* rL = rM + AQ;
    float* rC = rL + AQ;

    const int tid = threadIdx.x;
    const int lane = tid & 31;
    const int wid = tid >> 5;
    const int g = lane >> 2, t4 = lane & 3;
    const int wm = (wid & 3) * 16;     // warp row offset (4 warps over 64 rows)
    const int wn = (wid >> 2) * 128;   // warp col offset for PV/output (2 warps)
    const int wns = (wid >> 2) * 32;   // warp col offset for S (64 cols)

    const int b = blockIdx.y >> 4;
    const int h = blockIdx.y & 15;
    const int q0 = blockIdx.x * AQ;

    const float* qg = Q + ((size_t)(b * 512 + q0)) * 4096 + h * 256;
    const float* kg = Kk + ((size_t)(b * 512)) * 4096 + h * 256;
    const float* vg = V + ((size_t)(b * 512)) * 4096 + h * 256;
    const float* eg = EP + ((size_t)(b * 512 + q0)) * 8192 + h * 512;
    float* og = O + ((size_t)(b * 512 + q0)) * 4096 + h * 256;

    const float qscale = 0.0625f; // 1/sqrt(256)
    for (int i = tid; i < AQ * 64; i += 256) {
        int r = i >> 6, ccol = (i & 63) << 2;
        float4 qv = *(const float4*)(qg + (size_t)r * 4096 + ccol);
        *(uint4*)(Qs + r * QSTR + ccol) =
            make_uint4(f2tf(qv.x * qscale), f2tf(qv.y * qscale),
                       f2tf(qv.z * qscale), f2tf(qv.w * qscale));
    }
    if (tid < AQ) { rM[tid] = -1e30f; rL[tid] = 0.f; }

    float o[16][4];
#pragma unroll
    for (int nf = 0; nf < 16; nf++)
#pragma unroll
        for (int q = 0; q < 4; q++) o[nf][q] = 0.f;

    for (int kc = 0; kc < 8; kc++) {
        __syncthreads(); // previous users of Ks/Vs/Ss done (also guards Q load)
        for (int i = tid; i < AS * 64; i += 256) {
            int r = i >> 6, ccol = (i & 63) << 2;
            float4 kv = *(const float4*)(kg + (size_t)(kc * AS + r) * 4096 + ccol);
            float4 vv = *(const float4*)(vg + (size_t)(kc * AS + r) * 4096 + ccol);
            *(uint4*)(Ks + r * KSTR + ccol) =
                make_uint4(f2tf(kv.x), f2tf(kv.y), f2tf(kv.z), f2tf(kv.w));
            *(uint4*)(Vs + r * VSTR + ccol) =
                make_uint4(f2tf(vv.x), f2tf(vv.y), f2tf(vv.z), f2tf(vv.w));
        }
        __syncthreads();

        // ---- S = Q K^T : warp computes 16 x 32 ----
        float sacc[4][4];
#pragma unroll
        for (int nf = 0; nf < 4; nf++)
#pragma unroll
            for (int q = 0; q < 4; q++) sacc[nf][q] = 0.f;
#pragma unroll
        for (int ks = 0; ks < 32; ks++) {
            const int k0 = ks * 8;
            unsigned af[4];
            const float* pa = Qs + (wm + g) * QSTR + k0 + t4;
            af[0] = __float_as_uint(pa[0]);
            af[1] = __float_as_uint(pa[8 * QSTR]);
            af[2] = __float_as_uint(pa[4]);
            af[3] = __float_as_uint(pa[8 * QSTR + 4]);
#pragma unroll
            for (int nf = 0; nf < 4; nf++) {
                unsigned bf[2];
                const float* pb = Ks + (wns + nf * 8 + g) * KSTR + k0 + t4;
                bf[0] = __float_as_uint(pb[0]);
                bf[1] = __float_as_uint(pb[4]);
                MMA8(sacc[nf], af, bf);
            }
        }
#pragma unroll
        for (int nf = 0; nf < 4; nf++) {
            const int cc = wns + nf * 8 + 2 * t4;
            *(float2*)(Ss + (wm + g) * SSTR + cc) = make_float2(sacc[nf][0], sacc[nf][1]);
            *(float2*)(Ss + (wm + 8 + g) * SSTR + cc) = make_float2(sacc[nf][2], sacc[nf][3]);
        }
        __syncthreads();

        // ---- softmax (+ep bias) : 4 threads per row, 16 cols each ----
        {
            const int r = tid >> 2, sub = tid & 3;
            float sv[16];
            const float* ep4 = eg + (size_t)r * 8192 + kc * 64 + sub * 16;
            float* srow = Ss + r * SSTR + sub * 16;
#pragma unroll
            for (int j = 0; j < 4; j++) {
                float4 e = *(const float4*)(ep4 + j * 4);
                float4 s = *(const float4*)(srow + j * 4);
                sv[4 * j + 0] = s.x + e.x;
                sv[4 * j + 1] = s.y + e.y;
                sv[4 * j + 2] = s.z + e.z;
                sv[4 * j + 3] = s.w + e.w;
            }
            float mx = -1e30f;
#pragma unroll
            for (int j = 0; j < 16; j++) mx = fmaxf(mx, sv[j]);
            mx = fmaxf(mx, __shfl_xor_sync(0xffffffffu, mx, 1));
            mx = fmaxf(mx, __shfl_xor_sync(0xffffffffu, mx, 2));
            const float mold = rM[r];
            const float mnew = fmaxf(mold, mx);
            float sum = 0.f;
#pragma unroll
            for (int j = 0; j < 16; j++) {
                float p = __expf(sv[j] - mnew);
                sum += p;
                sv[j] = p;
            }
            sum += __shfl_xor_sync(0xffffffffu, sum, 1);
            sum += __shfl_xor_sync(0xffffffffu, sum, 2);
#pragma unroll
            for (int j = 0; j < 4; j++) {
                *(uint4*)(srow + j * 4) =
                    make_uint4(f2tf(sv[4 * j + 0]), f2tf(sv[4 * j + 1]),
                               f2tf(sv[4 * j + 2]), f2tf(sv[4 * j + 3]));
            }
            if (sub == 0) {
                const float corr = __expf(mold - mnew);
                rC[r] = corr;
                rM[r] = mnew;
                rL[r] = rL[r] * corr + sum;
            }
        }
        __syncthreads();

        // ---- rescale O, accumulate O += P V : warp computes 16 x 128 ----
        const float c0 = rC[wm + g], c1 = rC[wm + 8 + g];
#pragma unroll
        for (int nf = 0; nf < 16; nf++) {
            o[nf][0] *= c0; o[nf][1] *= c0;
            o[nf][2] *= c1; o[nf][3] *= c1;
        }
#pragma unroll
        for (int ks = 0; ks < 8; ks++) {
            const int k0 = ks * 8;
            unsigned af[4];
            const float* pa = Ss + (wm + g) * SSTR + k0 + t4;
            af[0] = __float_as_uint(pa[0]);
            af[1] = __float_as_uint(pa[8 * SSTR]);
            af[2] = __float_as_uint(pa[4]);
            af[3] = __float_as_uint(pa[8 * SSTR + 4]);
#pragma unroll
            for (int nf = 0; nf < 16; nf++) {
                unsigned bf[2];
                const float* pb = Vs + (k0 + t4) * VSTR + wn + nf * 8 + g;
                bf[0] = __float_as_uint(pb[0]);
                bf[1] = __float_as_uint(pb[4 * VSTR]);
                MMA8(o[nf], af, bf);
            }
        }
    }

    // ---- epilogue: O / l ----
    const float l0 = 1.f / rL[wm + g];
    const float l1 = 1.f / rL[wm + 8 + g];
#pragma unroll
    for (int nf = 0; nf < 16; nf++) {
        const int cc = wn + nf * 8 + 2 * t4;
        *(float2*)(og + (size_t)(wm + g) * 4096 + cc) =
            make_float2(o[nf][0] * l0, o[nf][1] * l0);
        *(float2*)(og + (size_t)(wm + 8 + g) * 4096 + cc) =
            make_float2(o[nf][2] * l1, o[nf][3] * l1);
    }
}

// ---------------- launch ------------------------------------------------------
extern "C" void kernel_launch(void* const* d_in, const int* in_sizes, int n_in,
                              void* d_out, int out_size) {
    (void)in_sizes; (void)n_in; (void)out_size;
    const float* x   = (const float*)d_in[0];
    const float* aug = (const float*)d_in[1];
    const float* Wq  = (const float*)d_in[2];
    const float* Wk  = (const float*)d_in[3];
    const float* Wv  = (const float*)d_in[4];
    const float* Wp  = (const float*)d_in[5];
    const float* bp  = (const float*)d_in[6];
    float* out = (float*)d_out;

    float *gq, *gk, *gv, *gep;
    cudaGetSymbolAddress((void**)&gq, g_q);
    cudaGetSymbolAddress((void**)&gk, g_k);
    cudaGetSymbolAddress((void**)&gv, g_v);
    cudaGetSymbolAddress((void**)&gep, g_ep);

    cudaFuncSetAttribute(gemm_tf32, cudaFuncAttributeMaxDynamicSharedMemorySize, GEMM_SMEM);
    cudaFuncSetAttribute(attn_tf32, cudaFuncAttributeMaxDynamicSharedMemorySize, ATTN_SMEM);

    dim3 blk(256);
    dim3 gqkv(4096 / GBN, 8192 / GBM);
    gemm_tf32<<<gqkv, blk, GEMM_SMEM>>>(x, Wq, nullptr, gq, 8192, 4096, 4096);
    gemm_tf32<<<gqkv, blk, GEMM_SMEM>>>(x, Wk, nullptr, gk, 8192, 4096, 4096);
    gemm_tf32<<<gqkv, blk, GEMM_SMEM>>>(x, Wv, nullptr, gv, 8192, 4096, 4096);

    dim3 gep_grid(8192 / GBN, 8192 / GBM);
    gemm_tf32<<<gep_grid, blk, GEMM_SMEM>>>(aug, Wp, bp, gep, 8192, 8192, 4096);

    dim3 gattn(512 / AQ, 16 * 16);
    attn_tf32<<<gattn, blk, ATTN_SMEM>>>(gq, gk, gv, gep, out);
}